// round 15
// baseline (speedup 1.0000x reference)
#include <cuda_runtime.h>
#include <cuda_fp16.h>
#include <cstdint>

// LIIF render via fp16 HMMA (mma.sync m16n8k16) on sm_103.
// R15 = R13/R14 (best: 1329.6us) +
//   (1) fragment-ordered B strips in gmem -> 2x LDS.128 per s-step (was 8x LDS.32)
//   (2) two q-tiles per CTA (grid 1024x4): setup amortized, waves halved,
//       tile-1 stage-0 copy overlapped with tile-0 tail + h0.
// Mainloop mma/Xs/h0/epilogue arithmetic identical to R13.

namespace {

constexpr int NTHR    = 256;
constexpr int QT      = 32;
constexpr int XS_H    = 264;               // X row stride in halves (132 words)
constexpr int BWW     = 1152;              // B strip buffer size in words (4608B)
constexpr int NSTAGES = 12;                // 3 layers x 4 k-tiles of 64

__device__ uint32_t g_wf[3 * 8 * 4 * 1152];   // w1..w3, fragment-ordered strips
__device__ __half   g_proj_h[4 * 4096 * 256]; // P' fp16

__device__ __forceinline__ void cp16(uint32_t dst, const void* src) {
    asm volatile("cp.async.cg.shared.global [%0], [%1], 16;"
                 :: "r"(dst), "l"(src) : "memory");
}
__device__ __forceinline__ void cp_commit() {
    asm volatile("cp.async.commit_group;" ::: "memory");
}
template <int N>
__device__ __forceinline__ void cp_wait() {
    asm volatile("cp.async.wait_group %0;" :: "n"(N) : "memory");
}
__device__ __forceinline__ uint32_t smem_u32(const void* p) {
    uint32_t a;
    asm("{ .reg .u64 t; cvta.to.shared.u64 t, %1; cvt.u32.u64 %0, t; }"
        : "=r"(a) : "l"(p));
    return a;
}
__device__ __forceinline__ void lds128(uint32_t& r0, uint32_t& r1,
                                       uint32_t& r2, uint32_t& r3, uint32_t addr) {
    asm volatile("ld.shared.v4.u32 {%0,%1,%2,%3}, [%4];"
                 : "=r"(r0), "=r"(r1), "=r"(r2), "=r"(r3) : "r"(addr));
}
__device__ __forceinline__ void ldsm4(uint32_t& r0, uint32_t& r1,
                                      uint32_t& r2, uint32_t& r3, uint32_t addr) {
    asm volatile("ldmatrix.sync.aligned.m8n8.x4.shared.b16 {%0,%1,%2,%3}, [%4];"
                 : "=r"(r0), "=r"(r1), "=r"(r2), "=r"(r3) : "r"(addr));
}
__device__ __forceinline__ void mma_f16(float c[4], uint32_t a0, uint32_t a1,
                                        uint32_t a2, uint32_t a3,
                                        uint32_t b0, uint32_t b1) {
    asm volatile(
        "mma.sync.aligned.m16n8k16.row.col.f32.f16.f16.f32 "
        "{%0,%1,%2,%3}, {%4,%5,%6,%7}, {%8,%9}, {%0,%1,%2,%3};"
        : "+f"(c[0]), "+f"(c[1]), "+f"(c[2]), "+f"(c[3])
        : "r"(a0), "r"(a1), "r"(a2), "r"(a3), "r"(b0), "r"(b1));
}

// ---------- fused prep ----------
// blocks 0..127   : P' build via fp16 HMMA (w0 transposed in-block, R14-validated)
// blocks 128..511 : w1..w3 -> fragment-ordered fp16 strips in g_wf
__global__ __launch_bounds__(256, 1)
void prep_kernel(const float* __restrict__ feat,
                 const float* __restrict__ w0,
                 const float* __restrict__ b0,
                 const float* __restrict__ w1,
                 const float* __restrict__ w2,
                 const float* __restrict__ w3) {
    const int tid = threadIdx.x;

    if (blockIdx.x >= 128) {
        // element e -> (l, w, t, s, lane, j); j = nt*2 + h
        const int e = (blockIdx.x - 128) * 256 + tid;     // 0..98303
        const int j    = e & 7;
        const int lane = (e >> 3) & 31;
        const int s    = (e >> 8) & 3;
        const int t    = (e >> 10) & 3;
        const int w    = (e >> 12) & 7;
        const int l    = e >> 15;
        const float* wl = (l == 0) ? w1 : (l == 1) ? w2 : w3;
        const int g  = lane >> 2, tg = lane & 3;
        const int n  = w * 32 + (j >> 1) * 8 + g;
        const int k0 = t * 64 + 16 * s + 2 * tg + 8 * (j & 1);
        const __half2 v = __floats2half2_rn(wl[k0 * 256 + n], wl[(k0 + 1) * 256 + n]);
        const int addr = ((l * 8 + w) * 4 + t) * BWW
                       + s * 288 + lane * 8 + (lane >> 2) * 4 + j;
        g_wf[addr] = *(const uint32_t*)&v;
        return;
    }

    // ---- P' build: 128 cells of one image via fp16 HMMA (identical to R14) ----
    extern __shared__ __half pps[];
    __half* A   = pps;                        // 128 cells x 72 halves (k-major)
    __half* Bst = pps + 128 * 72;             // 8 warps x 32 n x 72 halves
    float*  bf  = (float*)(pps + 128 * 72 + 8 * 32 * 72);   // 256 bias
    const uint32_t a_u = smem_u32(A);

    const int blk   = blockIdx.x;             // 0..127
    const int n     = blk >> 5;
    const int cell0 = (blk & 31) << 7;
    const int wid   = tid >> 5;
    const int lane  = tid & 31;
    const int g_    = lane >> 2, tig = lane & 3;

    {
        const int nn = wid * 32 + lane;
        __half* bd = Bst + (size_t)(wid * 32 + lane) * 72;
#pragma unroll 16
        for (int k = 0; k < 64; k++)
            bd[k] = __float2half_rn(w0[k * 256 + nn]);
    }
    bf[tid] = b0[tid] + 0.5f * (w0[66 * 256 + tid] + w0[67 * 256 + tid]);
#pragma unroll
    for (int j = 0; j < 8; j++) {
        const int e = tid + 256 * j;
        const int ch = e >> 5, c4 = e & 31;
        const float4 v = ((const float4*)feat)[(((size_t)n * 64 + ch) << 10)
                                               + (cell0 >> 2) + c4];
        A[(4 * c4 + 0) * 72 + ch] = __float2half_rn(v.x);
        A[(4 * c4 + 1) * 72 + ch] = __float2half_rn(v.y);
        A[(4 * c4 + 2) * 72 + ch] = __float2half_rn(v.z);
        A[(4 * c4 + 3) * 72 + ch] = __float2half_rn(v.w);
    }
    __syncthreads();

    const uint32_t a_lane = a_u + (uint32_t)((lane & 15) * 72 + ((lane >> 4) << 3)) * 2u;
    const uint32_t* Bb = (const uint32_t*)(Bst + wid * 32 * 72);

    float acc[8][4][4];
#pragma unroll
    for (int mt = 0; mt < 8; mt++)
#pragma unroll
        for (int nt = 0; nt < 4; nt++)
#pragma unroll
            for (int r = 0; r < 4; r++) acc[mt][nt][r] = 0.f;

#pragma unroll
    for (int s = 0; s < 4; s++) {
        uint32_t b0f[4], b1f[4];
#pragma unroll
        for (int nt = 0; nt < 4; nt++) {
            const int bw = (nt * 8 + g_) * 36 + s * 8 + tig;
            b0f[nt] = Bb[bw];
            b1f[nt] = Bb[bw + 4];
        }
        const uint32_t a_s = a_lane + (uint32_t)(s * 32);
#pragma unroll
        for (int mt = 0; mt < 8; mt++) {
            uint32_t a0, a1, a2, a3;
            ldsm4(a0, a1, a2, a3, a_s + (uint32_t)(mt * 16 * 72 * 2));
#pragma unroll
            for (int nt = 0; nt < 4; nt++)
                mma_f16(acc[mt][nt], a0, a1, a2, a3, b0f[nt], b1f[nt]);
        }
    }

    __half2* out2 = (__half2*)(g_proj_h + (((size_t)n << 12) + cell0) * 256);
#pragma unroll
    for (int mt = 0; mt < 8; mt++) {
#pragma unroll
        for (int nt = 0; nt < 4; nt++) {
            const int c = wid * 32 + nt * 8 + 2 * tig;
            const float bv0 = bf[c], bv1 = bf[c + 1];
            const int r0 = mt * 16 + g_;
            out2[r0 * 128 + (c >> 1)] =
                __floats2half2_rn(acc[mt][nt][0] + bv0, acc[mt][nt][1] + bv1);
            out2[(r0 + 8) * 128 + (c >> 1)] =
                __floats2half2_rn(acc[mt][nt][2] + bv0, acc[mt][nt][3] + bv1);
        }
    }
}

// ---------- main kernel: 2 q-tiles per CTA ----------
__global__ __launch_bounds__(NTHR, 1)
void liif_hmma_kernel(const float* __restrict__ w0, const float* __restrict__ w4,
                      const float* __restrict__ b1, const float* __restrict__ b2,
                      const float* __restrict__ b3, const float* __restrict__ b4,
                      float* __restrict__ out)
{
    extern __shared__ __half smem_h[];
    __half*   Xs = smem_h;                        // 128 x 264 halves
    uint32_t* Bs = (uint32_t*)(smem_h + 128 * XS_H); // 8 warps x 2 bufs x 1152 words
    const uint32_t xs_u = smem_u32(Xs);
    const uint32_t bs_u = smem_u32(Bs);

    __shared__ float s_bias[3][256];
    __shared__ float s_w0r[2][256];
    __shared__ float s_w4[772];
    __shared__ float s_b4[3];
    __shared__ int   s_idx[4][QT];
    __shared__ float s_rel[4][2][QT];
    __shared__ float s_area[4][QT];
    __shared__ float s_wt[4][QT];
    __shared__ float s_red[128][2][3];

    const int tid  = threadIdx.x;
    const int wid  = tid >> 5;
    const int lane = tid & 31;
    const int g_   = lane >> 2, tig = lane & 3;
    const int n    = blockIdx.y;

    // per-warp strip copy: stage st -> buffer buf (verbatim 4608B, 9 cp16/lane)
    auto prefetch = [&](int buf, int st) {
        const uint32_t* src = g_wf + (((st >> 2) * 8 + wid) * 4 + (st & 3)) * BWW;
        const uint32_t dst0 = bs_u + (uint32_t)((wid * 2 + buf) * BWW) * 4u;
#pragma unroll
        for (int i = 0; i < 9; i++) {
            const int c = lane + 32 * i;
            cp16(dst0 + (uint32_t)c * 16u, src + c * 4);
        }
        cp_commit();
    };

    prefetch(0, 0);     // tile-0 stage 0 in flight during setup

    for (int i = tid; i < 256; i += NTHR) {
        s_bias[0][i] = b1[i]; s_bias[1][i] = b2[i]; s_bias[2][i] = b3[i];
        s_w0r[0][i] = w0[64 * 256 + i]; s_w0r[1][i] = w0[65 * 256 + i];
    }
    for (int i = tid; i < 768; i += NTHR) s_w4[i] = w4[i];
    if (tid < 3) s_b4[tid] = b4[tid];

    const int lrow = lane & 15;
    const int kadd = (lane >> 4) << 3;
    const uint32_t a_lane = xs_u + (uint32_t)(lrow * XS_H + kadd) * 2u;
    const uint32_t b_lane = (uint32_t)(lane * 8 + (lane >> 2) * 4) * 4u;   // bytes

    float acc[8][4][4];
#pragma unroll
    for (int mt = 0; mt < 8; mt++)
#pragma unroll
        for (int nt = 0; nt < 4; nt++)
#pragma unroll
            for (int r = 0; r < 4; r++) acc[mt][nt][r] = 0.f;

    int buf = 0;

#pragma unroll 1
    for (int tile_i = 0; tile_i < 2; tile_i++) {
        const int q0 = (blockIdx.x * 2 + tile_i) * QT;

        // per-query geometry, one corner per thread (validated R1/R3)
        if (tid < 128) {
            const int t = tid >> 5, i = tid & 31;
            const int q = q0 + i;
            const int yq = q >> 8, xq = q & 255;
            const float c0 = (2.f * (float)yq + 1.f) * (1.f / 256.f) - 1.f;
            const float c1 = (2.f * (float)xq + 1.f) * (1.f / 256.f) - 1.f;
            const float lo = (float)(-1.0 + 1e-6), hi = (float)(1.0 - 1e-6);
            const double vx = (t < 2) ? -1.0 : 1.0;
            const double vy = (t & 1) ? 1.0 : -1.0;
            const float shx = (float)(vx * (1.0 / 64.0) + 1e-6);
            const float shy = (float)(vy * (1.0 / 64.0) + 1e-6);
            const float cc0 = fminf(fmaxf(c0 + shx, lo), hi);
            const float cc1 = fminf(fmaxf(c1 + shy, lo), hi);
            int iy = (int)rintf(((cc0 + 1.f) * 64.f - 1.f) * 0.5f);
            int ix = (int)rintf(((cc1 + 1.f) * 64.f - 1.f) * 0.5f);
            iy = min(max(iy, 0), 63); ix = min(max(ix, 0), 63);
            const float qc0 = (2.f * (float)iy + 1.f) * (1.f / 64.f) - 1.f;
            const float qc1 = (2.f * (float)ix + 1.f) * (1.f / 64.f) - 1.f;
            const float r0 = (c0 - qc0) * 64.f;
            const float r1 = (c1 - qc1) * 64.f;
            s_idx[t][i] = iy * 64 + ix;
            s_rel[t][0][i] = r0; s_rel[t][1][i] = r1;
            s_area[t][i] = fabsf(r0 * r1) + 1e-9f;
        }
        __syncthreads();

        if (tid < QT) {
            const float a0 = s_area[0][tid], a1 = s_area[1][tid];
            const float a2 = s_area[2][tid], a3 = s_area[3][tid];
            const float tot = a0 + a1 + a2 + a3;
            s_wt[0][tid] = a3 / tot; s_wt[1][tid] = a2 / tot;
            s_wt[2][tid] = a1 / tot; s_wt[3][tid] = a0 / tot;
        }

        // h0 build: thread = (row, 128-col half); P' fp16 -> fp32 math -> fp16
        {
            const int row = tid >> 1, hseg = tid & 1;
            const int t = row >> 5, i = row & 31;
            const int idx = s_idx[t][i];
            const float r0 = s_rel[t][0][i], r1 = s_rel[t][1][i];
            const uint4* pp = (const uint4*)(g_proj_h + (((size_t)n << 12) + idx) * 256
                                             + hseg * 128);
            __half2* xw = (__half2*)Xs + row * 132 + hseg * 64;
#pragma unroll
            for (int j = 0; j < 16; j++) {
                const uint4 q = pp[j];
                uint32_t w[4] = {q.x, q.y, q.z, q.w};
                const int cb = hseg * 128 + j * 8;
#pragma unroll
                for (int u = 0; u < 4; u++) {
                    const float2 p = __half22float2(*(const __half2*)&w[u]);
                    const int c = cb + 2 * u;
                    const float v0 = fmaf(r0, s_w0r[0][c],     fmaf(r1, s_w0r[1][c],     p.x));
                    const float v1 = fmaf(r0, s_w0r[0][c + 1], fmaf(r1, s_w0r[1][c + 1], p.y));
                    xw[j * 4 + u] = __floats2half2_rn(fmaxf(v0, 0.f), fmaxf(v1, 0.f));
                }
            }
        }
        __syncthreads();

#pragma unroll 1
        for (int st = 0; st < NSTAGES; st++) {
            const int tile = st & 3;

            if (st + 1 < NSTAGES)       { prefetch(buf ^ 1, st + 1); cp_wait<1>(); }
            else if (tile_i == 0)       { prefetch(buf ^ 1, 0);      cp_wait<1>(); }
            else                        { cp_wait<0>(); }
            // no __syncthreads: B strips are warp-private, Xs is read-only here

            const uint32_t bbase = bs_u + (uint32_t)((wid * 2 + buf) * BWW) * 4u + b_lane;
            const uint32_t a_st  = a_lane + (uint32_t)(tile * 64) * 2u;

#pragma unroll
            for (int s = 0; s < 4; s++) {        // four k16 steps per 64-k tile
                uint32_t b0f[4], b1f[4];
                {
                    const uint32_t baddr = bbase + (uint32_t)(s * 288) * 4u;
                    lds128(b0f[0], b1f[0], b0f[1], b1f[1], baddr);
                    lds128(b0f[2], b1f[2], b0f[3], b1f[3], baddr + 16u);
                }
                const uint32_t a_s = a_st + (uint32_t)(s * 32);
#pragma unroll
                for (int mt = 0; mt < 8; mt++) {
                    uint32_t a0, a1, a2, a3;
                    ldsm4(a0, a1, a2, a3, a_s + (uint32_t)(mt * 16 * XS_H * 2));
#pragma unroll
                    for (int nt = 0; nt < 4; nt++)
                        mma_f16(acc[mt][nt], a0, a1, a2, a3, b0f[nt], b1f[nt]);
                }
            }
            buf ^= 1;

            if (tile == 3) {                     // layer boundary
                const int le = st >> 2;
                __syncthreads();                 // all reads of Xs done
#pragma unroll
                for (int mt = 0; mt < 8; mt++) {
#pragma unroll
                    for (int nt = 0; nt < 4; nt++) {
                        const int c = wid * 32 + nt * 8 + 2 * tig;
                        const float bv0 = s_bias[le][c], bv1 = s_bias[le][c + 1];
                        const float v00 = fmaxf(acc[mt][nt][0] + bv0, 0.f);
                        const float v01 = fmaxf(acc[mt][nt][1] + bv1, 0.f);
                        const float v10 = fmaxf(acc[mt][nt][2] + bv0, 0.f);
                        const float v11 = fmaxf(acc[mt][nt][3] + bv1, 0.f);
                        const int r0 = mt * 16 + g_;
                        __half2* xw = (__half2*)Xs;
                        xw[r0 * 132 + wid * 16 + nt * 4 + tig]       = __floats2half2_rn(v00, v01);
                        xw[(r0 + 8) * 132 + wid * 16 + nt * 4 + tig] = __floats2half2_rn(v10, v11);
                        acc[mt][nt][0] = 0.f; acc[mt][nt][1] = 0.f;
                        acc[mt][nt][2] = 0.f; acc[mt][nt][3] = 0.f;
                    }
                }
                __syncthreads();                 // writes visible before next layer
            }
        }

        // final 256->3 layer, fp32: thread = (row, k-half)
        {
            const int row = tid >> 1, hseg = tid & 1;
            const __half2* xw = (const __half2*)Xs + row * 132 + hseg * 64;
            float a0 = 0.f, a1 = 0.f, a2 = 0.f;
#pragma unroll 16
            for (int j = 0; j < 64; j++) {
                const float2 y = __half22float2(xw[j]);
                const float* wr = &s_w4[(hseg * 128 + 2 * j) * 3];
                a0 = fmaf(y.x, wr[0], fmaf(y.y, wr[3], a0));
                a1 = fmaf(y.x, wr[1], fmaf(y.y, wr[4], a1));
                a2 = fmaf(y.x, wr[2], fmaf(y.y, wr[5], a2));
            }
            s_red[row][hseg][0] = a0; s_red[row][hseg][1] = a1; s_red[row][hseg][2] = a2;
        }
        __syncthreads();

        // area-weighted combine + NCHW write
        if (tid < 96) {
            const int i = tid / 3;
            const int o = tid - 3 * (tid / 3);
            float v = 0.f;
#pragma unroll
            for (int t = 0; t < 4; t++) {
                const int row = t * 32 + i;
                const float p = s_b4[o] + s_red[row][0][o] + s_red[row][1][o];
                v += s_wt[t][i] * p;
            }
            out[((size_t)n * 3 + o) * 65536 + q0 + i] = v;
        }
        __syncthreads();   // writeout (reads s_wt/s_red) done before next tile reuses
    }
}

} // anonymous namespace

extern "C" void kernel_launch(void* const* d_in, const int* in_sizes, int n_in,
                              void* d_out, int out_size)
{
    (void)in_sizes; (void)n_in; (void)out_size;
    const float* feat = (const float*)d_in[0];
    const float* w0 = (const float*)d_in[1];
    const float* b0 = (const float*)d_in[2];
    const float* w1 = (const float*)d_in[3];
    const float* b1 = (const float*)d_in[4];
    const float* w2 = (const float*)d_in[5];
    const float* b2 = (const float*)d_in[6];
    const float* w3 = (const float*)d_in[7];
    const float* b3 = (const float*)d_in[8];
    const float* w4 = (const float*)d_in[9];
    const float* b4 = (const float*)d_in[10];

    const size_t prep_shmem = (128 * 72 + 8 * 32 * 72) * sizeof(__half)
                            + 256 * sizeof(float);               // 56320 B
    cudaFuncSetAttribute(prep_kernel,
                         cudaFuncAttributeMaxDynamicSharedMemorySize, (int)prep_shmem);
    prep_kernel<<<128 + 384, 256, prep_shmem>>>(feat, w0, b0, w1, w2, w3);

    const size_t shmem = (size_t)(128 * XS_H) * sizeof(__half)
                       + (size_t)(8 * 2 * BWW) * sizeof(uint32_t); // 141312 B
    cudaFuncSetAttribute(liif_hmma_kernel,
                         cudaFuncAttributeMaxDynamicSharedMemorySize, (int)shmem);
    dim3 grid(65536 / (QT * 2), 4);
    liif_hmma_kernel<<<grid, NTHR, shmem>>>(w0, w4, b1, b2, b3, b4, (float*)d_out);
}

// round 16
// speedup vs baseline: 1.5310x; 1.5310x over previous
#include <cuda_runtime.h>
#include <cuda_fp16.h>
#include <cstdint>

// LIIF render via fp16 HMMA (mma.sync m16n8k16) on sm_103.
// R16 = R13 (best: 1329.6us) + ONLY the fragment-ordered B strips
// (2x LDS.128 per s-step instead of 8x LDS.32). One q-tile per CTA,
// structure otherwise byte-identical to R13.

namespace {

constexpr int NTHR    = 256;
constexpr int QT      = 32;
constexpr int XS_H    = 264;               // X row stride in halves (132 words)
constexpr int BWW     = 1152;              // B strip buffer size in words (4608B)
constexpr int NSTAGES = 12;                // 3 layers x 4 k-tiles of 64

__device__ uint32_t g_wf[3 * 8 * 4 * 1152];   // w1..w3, fragment-ordered strips
__device__ __half   g_proj_h[4 * 4096 * 256]; // P' fp16

__device__ __forceinline__ void cp16(uint32_t dst, const void* src) {
    asm volatile("cp.async.cg.shared.global [%0], [%1], 16;"
                 :: "r"(dst), "l"(src) : "memory");
}
__device__ __forceinline__ void cp_commit() {
    asm volatile("cp.async.commit_group;" ::: "memory");
}
template <int N>
__device__ __forceinline__ void cp_wait() {
    asm volatile("cp.async.wait_group %0;" :: "n"(N) : "memory");
}
__device__ __forceinline__ uint32_t smem_u32(const void* p) {
    uint32_t a;
    asm("{ .reg .u64 t; cvta.to.shared.u64 t, %1; cvt.u32.u64 %0, t; }"
        : "=r"(a) : "l"(p));
    return a;
}
__device__ __forceinline__ void lds128(uint32_t& r0, uint32_t& r1,
                                       uint32_t& r2, uint32_t& r3, uint32_t addr) {
    asm volatile("ld.shared.v4.u32 {%0,%1,%2,%3}, [%4];"
                 : "=r"(r0), "=r"(r1), "=r"(r2), "=r"(r3) : "r"(addr));
}
__device__ __forceinline__ void ldsm4(uint32_t& r0, uint32_t& r1,
                                      uint32_t& r2, uint32_t& r3, uint32_t addr) {
    asm volatile("ldmatrix.sync.aligned.m8n8.x4.shared.b16 {%0,%1,%2,%3}, [%4];"
                 : "=r"(r0), "=r"(r1), "=r"(r2), "=r"(r3) : "r"(addr));
}
__device__ __forceinline__ void mma_f16(float c[4], uint32_t a0, uint32_t a1,
                                        uint32_t a2, uint32_t a3,
                                        uint32_t b0, uint32_t b1) {
    asm volatile(
        "mma.sync.aligned.m16n8k16.row.col.f32.f16.f16.f32 "
        "{%0,%1,%2,%3}, {%4,%5,%6,%7}, {%8,%9}, {%0,%1,%2,%3};"
        : "+f"(c[0]), "+f"(c[1]), "+f"(c[2]), "+f"(c[3])
        : "r"(a0), "r"(a1), "r"(a2), "r"(a3), "r"(b0), "r"(b1));
}

// ---------- fused prep (validated R14/R15; rel_err bit-identical) ----------
// blocks 0..127   : P' build via fp16 HMMA (w0 transposed in-block)
// blocks 128..511 : w1..w3 -> fragment-ordered fp16 strips in g_wf
__global__ __launch_bounds__(256, 1)
void prep_kernel(const float* __restrict__ feat,
                 const float* __restrict__ w0,
                 const float* __restrict__ b0,
                 const float* __restrict__ w1,
                 const float* __restrict__ w2,
                 const float* __restrict__ w3) {
    const int tid = threadIdx.x;

    if (blockIdx.x >= 128) {
        const int e = (blockIdx.x - 128) * 256 + tid;     // 0..98303
        const int j    = e & 7;
        const int lane = (e >> 3) & 31;
        const int s    = (e >> 8) & 3;
        const int t    = (e >> 10) & 3;
        const int w    = (e >> 12) & 7;
        const int l    = e >> 15;
        const float* wl = (l == 0) ? w1 : (l == 1) ? w2 : w3;
        const int g  = lane >> 2, tg = lane & 3;
        const int n  = w * 32 + (j >> 1) * 8 + g;
        const int k0 = t * 64 + 16 * s + 2 * tg + 8 * (j & 1);
        const __half2 v = __floats2half2_rn(wl[k0 * 256 + n], wl[(k0 + 1) * 256 + n]);
        const int addr = ((l * 8 + w) * 4 + t) * BWW
                       + s * 288 + lane * 8 + (lane >> 2) * 4 + j;
        g_wf[addr] = *(const uint32_t*)&v;
        return;
    }

    extern __shared__ __half pps[];
    __half* A   = pps;                        // 128 cells x 72 halves (k-major)
    __half* Bst = pps + 128 * 72;             // 8 warps x 32 n x 72 halves
    float*  bf  = (float*)(pps + 128 * 72 + 8 * 32 * 72);   // 256 bias
    const uint32_t a_u = smem_u32(A);

    const int blk   = blockIdx.x;             // 0..127
    const int n     = blk >> 5;
    const int cell0 = (blk & 31) << 7;
    const int wid   = tid >> 5;
    const int lane  = tid & 31;
    const int g_    = lane >> 2, tig = lane & 3;

    {
        const int nn = wid * 32 + lane;
        __half* bd = Bst + (size_t)(wid * 32 + lane) * 72;
#pragma unroll 16
        for (int k = 0; k < 64; k++)
            bd[k] = __float2half_rn(w0[k * 256 + nn]);
    }
    bf[tid] = b0[tid] + 0.5f * (w0[66 * 256 + tid] + w0[67 * 256 + tid]);
#pragma unroll
    for (int j = 0; j < 8; j++) {
        const int e = tid + 256 * j;
        const int ch = e >> 5, c4 = e & 31;
        const float4 v = ((const float4*)feat)[(((size_t)n * 64 + ch) << 10)
                                               + (cell0 >> 2) + c4];
        A[(4 * c4 + 0) * 72 + ch] = __float2half_rn(v.x);
        A[(4 * c4 + 1) * 72 + ch] = __float2half_rn(v.y);
        A[(4 * c4 + 2) * 72 + ch] = __float2half_rn(v.z);
        A[(4 * c4 + 3) * 72 + ch] = __float2half_rn(v.w);
    }
    __syncthreads();

    const uint32_t a_lane = a_u + (uint32_t)((lane & 15) * 72 + ((lane >> 4) << 3)) * 2u;
    const uint32_t* Bb = (const uint32_t*)(Bst + wid * 32 * 72);

    float acc[8][4][4];
#pragma unroll
    for (int mt = 0; mt < 8; mt++)
#pragma unroll
        for (int nt = 0; nt < 4; nt++)
#pragma unroll
            for (int r = 0; r < 4; r++) acc[mt][nt][r] = 0.f;

#pragma unroll
    for (int s = 0; s < 4; s++) {
        uint32_t b0f[4], b1f[4];
#pragma unroll
        for (int nt = 0; nt < 4; nt++) {
            const int bw = (nt * 8 + g_) * 36 + s * 8 + tig;
            b0f[nt] = Bb[bw];
            b1f[nt] = Bb[bw + 4];
        }
        const uint32_t a_s = a_lane + (uint32_t)(s * 32);
#pragma unroll
        for (int mt = 0; mt < 8; mt++) {
            uint32_t a0, a1, a2, a3;
            ldsm4(a0, a1, a2, a3, a_s + (uint32_t)(mt * 16 * 72 * 2));
#pragma unroll
            for (int nt = 0; nt < 4; nt++)
                mma_f16(acc[mt][nt], a0, a1, a2, a3, b0f[nt], b1f[nt]);
        }
    }

    __half2* out2 = (__half2*)(g_proj_h + (((size_t)n << 12) + cell0) * 256);
#pragma unroll
    for (int mt = 0; mt < 8; mt++) {
#pragma unroll
        for (int nt = 0; nt < 4; nt++) {
            const int c = wid * 32 + nt * 8 + 2 * tig;
            const float bv0 = bf[c], bv1 = bf[c + 1];
            const int r0 = mt * 16 + g_;
            out2[r0 * 128 + (c >> 1)] =
                __floats2half2_rn(acc[mt][nt][0] + bv0, acc[mt][nt][1] + bv1);
            out2[(r0 + 8) * 128 + (c >> 1)] =
                __floats2half2_rn(acc[mt][nt][2] + bv0, acc[mt][nt][3] + bv1);
        }
    }
}

// ---------- main kernel: R13 structure, LDS.128 B reads ----------
__global__ __launch_bounds__(NTHR, 1)
void liif_hmma_kernel(const float* __restrict__ w0, const float* __restrict__ w4,
                      const float* __restrict__ b1, const float* __restrict__ b2,
                      const float* __restrict__ b3, const float* __restrict__ b4,
                      float* __restrict__ out)
{
    extern __shared__ __half smem_h[];
    __half*   Xs = smem_h;                           // 128 x 264 halves
    uint32_t* Bs = (uint32_t*)(smem_h + 128 * XS_H); // 8 warps x 2 bufs x 1152 words
    const uint32_t xs_u = smem_u32(Xs);
    const uint32_t bs_u = smem_u32(Bs);

    __shared__ float s_bias[3][256];
    __shared__ float s_w0r[2][256];
    __shared__ float s_w4[772];
    __shared__ float s_b4[3];
    __shared__ int   s_idx[4][QT];
    __shared__ float s_rel[4][2][QT];
    __shared__ float s_area[4][QT];
    __shared__ float s_wt[4][QT];
    __shared__ float s_red[128][2][3];

    const int tid  = threadIdx.x;
    const int wid  = tid >> 5;
    const int lane = tid & 31;
    const int g_   = lane >> 2, tig = lane & 3;
    const int n    = blockIdx.y;
    const int q0   = blockIdx.x * QT;

    // per-warp strip copy: stage st -> buffer buf (4608B, 9 cp16/lane)
    auto prefetch = [&](int buf, int st) {
        const uint32_t* src = g_wf + (((st >> 2) * 8 + wid) * 4 + (st & 3)) * BWW;
        const uint32_t dst0 = bs_u + (uint32_t)((wid * 2 + buf) * BWW) * 4u;
#pragma unroll
        for (int i = 0; i < 9; i++) {
            const int c = lane + 32 * i;
            cp16(dst0 + (uint32_t)c * 16u, src + c * 4);
        }
        cp_commit();
    };

    prefetch(0, 0);     // stage 0 in flight during setup

    for (int i = tid; i < 256; i += NTHR) {
        s_bias[0][i] = b1[i]; s_bias[1][i] = b2[i]; s_bias[2][i] = b3[i];
        s_w0r[0][i] = w0[64 * 256 + i]; s_w0r[1][i] = w0[65 * 256 + i];
    }
    for (int i = tid; i < 768; i += NTHR) s_w4[i] = w4[i];
    if (tid < 3) s_b4[tid] = b4[tid];

    // per-query geometry, one corner per thread (validated R1/R3)
    if (tid < 128) {
        const int t = tid >> 5, i = tid & 31;
        const int q = q0 + i;
        const int yq = q >> 8, xq = q & 255;
        const float c0 = (2.f * (float)yq + 1.f) * (1.f / 256.f) - 1.f;
        const float c1 = (2.f * (float)xq + 1.f) * (1.f / 256.f) - 1.f;
        const float lo = (float)(-1.0 + 1e-6), hi = (float)(1.0 - 1e-6);
        const double vx = (t < 2) ? -1.0 : 1.0;
        const double vy = (t & 1) ? 1.0 : -1.0;
        const float shx = (float)(vx * (1.0 / 64.0) + 1e-6);
        const float shy = (float)(vy * (1.0 / 64.0) + 1e-6);
        const float cc0 = fminf(fmaxf(c0 + shx, lo), hi);
        const float cc1 = fminf(fmaxf(c1 + shy, lo), hi);
        int iy = (int)rintf(((cc0 + 1.f) * 64.f - 1.f) * 0.5f);
        int ix = (int)rintf(((cc1 + 1.f) * 64.f - 1.f) * 0.5f);
        iy = min(max(iy, 0), 63); ix = min(max(ix, 0), 63);
        const float qc0 = (2.f * (float)iy + 1.f) * (1.f / 64.f) - 1.f;
        const float qc1 = (2.f * (float)ix + 1.f) * (1.f / 64.f) - 1.f;
        const float r0 = (c0 - qc0) * 64.f;
        const float r1 = (c1 - qc1) * 64.f;
        s_idx[t][i] = iy * 64 + ix;
        s_rel[t][0][i] = r0; s_rel[t][1][i] = r1;
        s_area[t][i] = fabsf(r0 * r1) + 1e-9f;
    }
    __syncthreads();

    // area weights (read only after later barriers)
    if (tid < QT) {
        const float a0 = s_area[0][tid], a1 = s_area[1][tid];
        const float a2 = s_area[2][tid], a3 = s_area[3][tid];
        const float tot = a0 + a1 + a2 + a3;
        s_wt[0][tid] = a3 / tot; s_wt[1][tid] = a2 / tot;
        s_wt[2][tid] = a1 / tot; s_wt[3][tid] = a0 / tot;
    }

    // h0 build: thread = (row, 128-col half); P' fp16 -> fp32 math -> fp16
    {
        const int row = tid >> 1, hseg = tid & 1;
        const int t = row >> 5, i = row & 31;
        const int idx = s_idx[t][i];
        const float r0 = s_rel[t][0][i], r1 = s_rel[t][1][i];
        const uint4* pp = (const uint4*)(g_proj_h + (((size_t)n << 12) + idx) * 256
                                         + hseg * 128);
        __half2* xw = (__half2*)Xs + row * 132 + hseg * 64;
#pragma unroll
        for (int j = 0; j < 16; j++) {
            const uint4 q = pp[j];
            uint32_t w[4] = {q.x, q.y, q.z, q.w};
            const int cb = hseg * 128 + j * 8;
#pragma unroll
            for (int u = 0; u < 4; u++) {
                const float2 p = __half22float2(*(const __half2*)&w[u]);
                const int c = cb + 2 * u;
                const float v0 = fmaf(r0, s_w0r[0][c],     fmaf(r1, s_w0r[1][c],     p.x));
                const float v1 = fmaf(r0, s_w0r[0][c + 1], fmaf(r1, s_w0r[1][c + 1], p.y));
                xw[j * 4 + u] = __floats2half2_rn(fmaxf(v0, 0.f), fmaxf(v1, 0.f));
            }
        }
    }
    __syncthreads();

    // ldmatrix per-lane A base: row = lane&15, k-halves add = (lane>>4)*8
    const int lrow = lane & 15;
    const int kadd = (lane >> 4) << 3;
    const uint32_t a_lane = xs_u + (uint32_t)(lrow * XS_H + kadd) * 2u;
    const uint32_t b_lane = (uint32_t)(lane * 8 + (lane >> 2) * 4) * 4u;   // bytes

    float acc[8][4][4];
#pragma unroll
    for (int mt = 0; mt < 8; mt++)
#pragma unroll
        for (int nt = 0; nt < 4; nt++)
#pragma unroll
            for (int r = 0; r < 4; r++) acc[mt][nt][r] = 0.f;

    int buf = 0;
#pragma unroll 1
    for (int st = 0; st < NSTAGES; st++) {
        const int tile = st & 3;

        if (st + 1 < NSTAGES) { prefetch(buf ^ 1, st + 1); cp_wait<1>(); }
        else                  { cp_wait<0>(); }
        // no __syncthreads: B strips are warp-private, Xs is read-only here

        const uint32_t bbase = bs_u + (uint32_t)((wid * 2 + buf) * BWW) * 4u + b_lane;
        const uint32_t a_st  = a_lane + (uint32_t)(tile * 64) * 2u;

#pragma unroll
        for (int s = 0; s < 4; s++) {            // four k16 steps per 64-k tile
            uint32_t b0f[4], b1f[4];
            {
                const uint32_t baddr = bbase + (uint32_t)(s * 288) * 4u;
                lds128(b0f[0], b1f[0], b0f[1], b1f[1], baddr);
                lds128(b0f[2], b1f[2], b0f[3], b1f[3], baddr + 16u);
            }
            const uint32_t a_s = a_st + (uint32_t)(s * 32);
#pragma unroll
            for (int mt = 0; mt < 8; mt++) {
                uint32_t a0, a1, a2, a3;
                ldsm4(a0, a1, a2, a3, a_s + (uint32_t)(mt * 16 * XS_H * 2));
#pragma unroll
                for (int nt = 0; nt < 4; nt++)
                    mma_f16(acc[mt][nt], a0, a1, a2, a3, b0f[nt], b1f[nt]);
            }
        }
        buf ^= 1;

        if (tile == 3) {                         // layer boundary
            const int le = st >> 2;
            __syncthreads();                     // all reads of Xs done
#pragma unroll
            for (int mt = 0; mt < 8; mt++) {
#pragma unroll
                for (int nt = 0; nt < 4; nt++) {
                    const int c = wid * 32 + nt * 8 + 2 * tig;
                    const float bv0 = s_bias[le][c], bv1 = s_bias[le][c + 1];
                    const float v00 = fmaxf(acc[mt][nt][0] + bv0, 0.f);
                    const float v01 = fmaxf(acc[mt][nt][1] + bv1, 0.f);
                    const float v10 = fmaxf(acc[mt][nt][2] + bv0, 0.f);
                    const float v11 = fmaxf(acc[mt][nt][3] + bv1, 0.f);
                    const int r0 = mt * 16 + g_;
                    __half2* xw = (__half2*)Xs;
                    xw[r0 * 132 + wid * 16 + nt * 4 + tig]       = __floats2half2_rn(v00, v01);
                    xw[(r0 + 8) * 132 + wid * 16 + nt * 4 + tig] = __floats2half2_rn(v10, v11);
                    acc[mt][nt][0] = 0.f; acc[mt][nt][1] = 0.f;
                    acc[mt][nt][2] = 0.f; acc[mt][nt][3] = 0.f;
                }
            }
            __syncthreads();                     // writes visible before next layer
        }
    }

    // final 256->3 layer, fp32: thread = (row, k-half)
    {
        const int row = tid >> 1, hseg = tid & 1;
        const __half2* xw = (const __half2*)Xs + row * 132 + hseg * 64;
        float a0 = 0.f, a1 = 0.f, a2 = 0.f;
#pragma unroll 16
        for (int j = 0; j < 64; j++) {
            const float2 y = __half22float2(xw[j]);
            const float* wr = &s_w4[(hseg * 128 + 2 * j) * 3];
            a0 = fmaf(y.x, wr[0], fmaf(y.y, wr[3], a0));
            a1 = fmaf(y.x, wr[1], fmaf(y.y, wr[4], a1));
            a2 = fmaf(y.x, wr[2], fmaf(y.y, wr[5], a2));
        }
        s_red[row][hseg][0] = a0; s_red[row][hseg][1] = a1; s_red[row][hseg][2] = a2;
    }
    __syncthreads();

    // area-weighted combine + NCHW write
    if (tid < 96) {
        const int i = tid / 3;
        const int o = tid - 3 * (tid / 3);
        float v = 0.f;
#pragma unroll
        for (int t = 0; t < 4; t++) {
            const int row = t * 32 + i;
            const float p = s_b4[o] + s_red[row][0][o] + s_red[row][1][o];
            v += s_wt[t][i] * p;
        }
        out[((size_t)n * 3 + o) * 65536 + q0 + i] = v;
    }
}

} // anonymous namespace

extern "C" void kernel_launch(void* const* d_in, const int* in_sizes, int n_in,
                              void* d_out, int out_size)
{
    (void)in_sizes; (void)n_in; (void)out_size;
    const float* feat = (const float*)d_in[0];
    const float* w0 = (const float*)d_in[1];
    const float* b0 = (const float*)d_in[2];
    const float* w1 = (const float*)d_in[3];
    const float* b1 = (const float*)d_in[4];
    const float* w2 = (const float*)d_in[5];
    const float* b2 = (const float*)d_in[6];
    const float* w3 = (const float*)d_in[7];
    const float* b3 = (const float*)d_in[8];
    const float* w4 = (const float*)d_in[9];
    const float* b4 = (const float*)d_in[10];

    const size_t prep_shmem = (128 * 72 + 8 * 32 * 72) * sizeof(__half)
                            + 256 * sizeof(float);               // 56320 B
    cudaFuncSetAttribute(prep_kernel,
                         cudaFuncAttributeMaxDynamicSharedMemorySize, (int)prep_shmem);
    prep_kernel<<<128 + 384, 256, prep_shmem>>>(feat, w0, b0, w1, w2, w3);

    const size_t shmem = (size_t)(128 * XS_H) * sizeof(__half)
                       + (size_t)(8 * 2 * BWW) * sizeof(uint32_t); // 141312 B
    cudaFuncSetAttribute(liif_hmma_kernel,
                         cudaFuncAttributeMaxDynamicSharedMemorySize, (int)shmem);
    dim3 grid(65536 / QT, 4);
    liif_hmma_kernel<<<grid, NTHR, shmem>>>(w0, w4, b1, b2, b3, b4, (float*)d_out);
}

// round 17
// speedup vs baseline: 1.6317x; 1.0658x over previous
#include <cuda_runtime.h>
#include <cuda_fp16.h>
#include <cstdint>

// LIIF render via fp16 HMMA (mma.sync m16n8k16) on sm_103.
// R17 = R16 (best: 1277.5us) + final 256->3 layer FUSED into the last HMMA
// epilogue: per-thread partial dots from acc (no last Xs write, no re-read,
// two fewer barriers). Mainloop byte-identical to R16.

namespace {

constexpr int NTHR    = 256;
constexpr int QT      = 32;
constexpr int XS_H    = 264;               // X row stride in halves (132 words)
constexpr int BWW     = 1152;              // B strip buffer size in words (4608B)
constexpr int NSTAGES = 12;                // 3 layers x 4 k-tiles of 64

__device__ uint32_t g_wf[3 * 8 * 4 * 1152];   // w1..w3, fragment-ordered strips
__device__ __half   g_proj_h[4 * 4096 * 256]; // P' fp16

__device__ __forceinline__ void cp16(uint32_t dst, const void* src) {
    asm volatile("cp.async.cg.shared.global [%0], [%1], 16;"
                 :: "r"(dst), "l"(src) : "memory");
}
__device__ __forceinline__ void cp_commit() {
    asm volatile("cp.async.commit_group;" ::: "memory");
}
template <int N>
__device__ __forceinline__ void cp_wait() {
    asm volatile("cp.async.wait_group %0;" :: "n"(N) : "memory");
}
__device__ __forceinline__ uint32_t smem_u32(const void* p) {
    uint32_t a;
    asm("{ .reg .u64 t; cvta.to.shared.u64 t, %1; cvt.u32.u64 %0, t; }"
        : "=r"(a) : "l"(p));
    return a;
}
__device__ __forceinline__ void lds128(uint32_t& r0, uint32_t& r1,
                                       uint32_t& r2, uint32_t& r3, uint32_t addr) {
    asm volatile("ld.shared.v4.u32 {%0,%1,%2,%3}, [%4];"
                 : "=r"(r0), "=r"(r1), "=r"(r2), "=r"(r3) : "r"(addr));
}
__device__ __forceinline__ void ldsm4(uint32_t& r0, uint32_t& r1,
                                      uint32_t& r2, uint32_t& r3, uint32_t addr) {
    asm volatile("ldmatrix.sync.aligned.m8n8.x4.shared.b16 {%0,%1,%2,%3}, [%4];"
                 : "=r"(r0), "=r"(r1), "=r"(r2), "=r"(r3) : "r"(addr));
}
__device__ __forceinline__ void mma_f16(float c[4], uint32_t a0, uint32_t a1,
                                        uint32_t a2, uint32_t a3,
                                        uint32_t b0, uint32_t b1) {
    asm volatile(
        "mma.sync.aligned.m16n8k16.row.col.f32.f16.f16.f32 "
        "{%0,%1,%2,%3}, {%4,%5,%6,%7}, {%8,%9}, {%0,%1,%2,%3};"
        : "+f"(c[0]), "+f"(c[1]), "+f"(c[2]), "+f"(c[3])
        : "r"(a0), "r"(a1), "r"(a2), "r"(a3), "r"(b0), "r"(b1));
}

// ---------- fused prep (validated R14-R16; rel_err bit-identical) ----------
__global__ __launch_bounds__(256, 1)
void prep_kernel(const float* __restrict__ feat,
                 const float* __restrict__ w0,
                 const float* __restrict__ b0,
                 const float* __restrict__ w1,
                 const float* __restrict__ w2,
                 const float* __restrict__ w3) {
    const int tid = threadIdx.x;

    if (blockIdx.x >= 128) {
        const int e = (blockIdx.x - 128) * 256 + tid;     // 0..98303
        const int j    = e & 7;
        const int lane = (e >> 3) & 31;
        const int s    = (e >> 8) & 3;
        const int t    = (e >> 10) & 3;
        const int w    = (e >> 12) & 7;
        const int l    = e >> 15;
        const float* wl = (l == 0) ? w1 : (l == 1) ? w2 : w3;
        const int g  = lane >> 2, tg = lane & 3;
        const int n  = w * 32 + (j >> 1) * 8 + g;
        const int k0 = t * 64 + 16 * s + 2 * tg + 8 * (j & 1);
        const __half2 v = __floats2half2_rn(wl[k0 * 256 + n], wl[(k0 + 1) * 256 + n]);
        const int addr = ((l * 8 + w) * 4 + t) * BWW
                       + s * 288 + lane * 8 + (lane >> 2) * 4 + j;
        g_wf[addr] = *(const uint32_t*)&v;
        return;
    }

    extern __shared__ __half pps[];
    __half* A   = pps;                        // 128 cells x 72 halves (k-major)
    __half* Bst = pps + 128 * 72;             // 8 warps x 32 n x 72 halves
    float*  bf  = (float*)(pps + 128 * 72 + 8 * 32 * 72);   // 256 bias
    const uint32_t a_u = smem_u32(A);

    const int blk   = blockIdx.x;             // 0..127
    const int n     = blk >> 5;
    const int cell0 = (blk & 31) << 7;
    const int wid   = tid >> 5;
    const int lane  = tid & 31;
    const int g_    = lane >> 2, tig = lane & 3;

    {
        const int nn = wid * 32 + lane;
        __half* bd = Bst + (size_t)(wid * 32 + lane) * 72;
#pragma unroll 16
        for (int k = 0; k < 64; k++)
            bd[k] = __float2half_rn(w0[k * 256 + nn]);
    }
    bf[tid] = b0[tid] + 0.5f * (w0[66 * 256 + tid] + w0[67 * 256 + tid]);
#pragma unroll
    for (int j = 0; j < 8; j++) {
        const int e = tid + 256 * j;
        const int ch = e >> 5, c4 = e & 31;
        const float4 v = ((const float4*)feat)[(((size_t)n * 64 + ch) << 10)
                                               + (cell0 >> 2) + c4];
        A[(4 * c4 + 0) * 72 + ch] = __float2half_rn(v.x);
        A[(4 * c4 + 1) * 72 + ch] = __float2half_rn(v.y);
        A[(4 * c4 + 2) * 72 + ch] = __float2half_rn(v.z);
        A[(4 * c4 + 3) * 72 + ch] = __float2half_rn(v.w);
    }
    __syncthreads();

    const uint32_t a_lane = a_u + (uint32_t)((lane & 15) * 72 + ((lane >> 4) << 3)) * 2u;
    const uint32_t* Bb = (const uint32_t*)(Bst + wid * 32 * 72);

    float acc[8][4][4];
#pragma unroll
    for (int mt = 0; mt < 8; mt++)
#pragma unroll
        for (int nt = 0; nt < 4; nt++)
#pragma unroll
            for (int r = 0; r < 4; r++) acc[mt][nt][r] = 0.f;

#pragma unroll
    for (int s = 0; s < 4; s++) {
        uint32_t b0f[4], b1f[4];
#pragma unroll
        for (int nt = 0; nt < 4; nt++) {
            const int bw = (nt * 8 + g_) * 36 + s * 8 + tig;
            b0f[nt] = Bb[bw];
            b1f[nt] = Bb[bw + 4];
        }
        const uint32_t a_s = a_lane + (uint32_t)(s * 32);
#pragma unroll
        for (int mt = 0; mt < 8; mt++) {
            uint32_t a0, a1, a2, a3;
            ldsm4(a0, a1, a2, a3, a_s + (uint32_t)(mt * 16 * 72 * 2));
#pragma unroll
            for (int nt = 0; nt < 4; nt++)
                mma_f16(acc[mt][nt], a0, a1, a2, a3, b0f[nt], b1f[nt]);
        }
    }

    __half2* out2 = (__half2*)(g_proj_h + (((size_t)n << 12) + cell0) * 256);
#pragma unroll
    for (int mt = 0; mt < 8; mt++) {
#pragma unroll
        for (int nt = 0; nt < 4; nt++) {
            const int c = wid * 32 + nt * 8 + 2 * tig;
            const float bv0 = bf[c], bv1 = bf[c + 1];
            const int r0 = mt * 16 + g_;
            out2[r0 * 128 + (c >> 1)] =
                __floats2half2_rn(acc[mt][nt][0] + bv0, acc[mt][nt][1] + bv1);
            out2[(r0 + 8) * 128 + (c >> 1)] =
                __floats2half2_rn(acc[mt][nt][2] + bv0, acc[mt][nt][3] + bv1);
        }
    }
}

// ---------- main kernel ----------
__global__ __launch_bounds__(NTHR, 1)
void liif_hmma_kernel(const float* __restrict__ w0, const float* __restrict__ w4,
                      const float* __restrict__ b1, const float* __restrict__ b2,
                      const float* __restrict__ b3, const float* __restrict__ b4,
                      float* __restrict__ out)
{
    extern __shared__ __half smem_h[];
    __half*   Xs = smem_h;                           // 128 x 264 halves
    uint32_t* Bs = (uint32_t*)(smem_h + 128 * XS_H); // 8 warps x 2 bufs x 1152 words
    const uint32_t xs_u = smem_u32(Xs);
    const uint32_t bs_u = smem_u32(Bs);

    __shared__ float s_bias[3][256];
    __shared__ float s_w0r[2][256];
    __shared__ float s_w4[772];
    __shared__ float s_b4[3];
    __shared__ int   s_idx[4][QT];
    __shared__ float s_rel[4][2][QT];
    __shared__ float s_area[4][QT];
    __shared__ float s_wt[4][QT];
    __shared__ float s_red[128][8][3];               // per-warp final partials

    const int tid  = threadIdx.x;
    const int wid  = tid >> 5;
    const int lane = tid & 31;
    const int g_   = lane >> 2, tig = lane & 3;
    const int n    = blockIdx.y;
    const int q0   = blockIdx.x * QT;

    // per-warp strip copy: stage st -> buffer buf (4608B, 9 cp16/lane)
    auto prefetch = [&](int buf, int st) {
        const uint32_t* src = g_wf + (((st >> 2) * 8 + wid) * 4 + (st & 3)) * BWW;
        const uint32_t dst0 = bs_u + (uint32_t)((wid * 2 + buf) * BWW) * 4u;
#pragma unroll
        for (int i = 0; i < 9; i++) {
            const int c = lane + 32 * i;
            cp16(dst0 + (uint32_t)c * 16u, src + c * 4);
        }
        cp_commit();
    };

    prefetch(0, 0);     // stage 0 in flight during setup

    for (int i = tid; i < 256; i += NTHR) {
        s_bias[0][i] = b1[i]; s_bias[1][i] = b2[i]; s_bias[2][i] = b3[i];
        s_w0r[0][i] = w0[64 * 256 + i]; s_w0r[1][i] = w0[65 * 256 + i];
    }
    for (int i = tid; i < 768; i += NTHR) s_w4[i] = w4[i];
    if (tid < 3) s_b4[tid] = b4[tid];

    // per-query geometry, one corner per thread (validated R1/R3)
    if (tid < 128) {
        const int t = tid >> 5, i = tid & 31;
        const int q = q0 + i;
        const int yq = q >> 8, xq = q & 255;
        const float c0 = (2.f * (float)yq + 1.f) * (1.f / 256.f) - 1.f;
        const float c1 = (2.f * (float)xq + 1.f) * (1.f / 256.f) - 1.f;
        const float lo = (float)(-1.0 + 1e-6), hi = (float)(1.0 - 1e-6);
        const double vx = (t < 2) ? -1.0 : 1.0;
        const double vy = (t & 1) ? 1.0 : -1.0;
        const float shx = (float)(vx * (1.0 / 64.0) + 1e-6);
        const float shy = (float)(vy * (1.0 / 64.0) + 1e-6);
        const float cc0 = fminf(fmaxf(c0 + shx, lo), hi);
        const float cc1 = fminf(fmaxf(c1 + shy, lo), hi);
        int iy = (int)rintf(((cc0 + 1.f) * 64.f - 1.f) * 0.5f);
        int ix = (int)rintf(((cc1 + 1.f) * 64.f - 1.f) * 0.5f);
        iy = min(max(iy, 0), 63); ix = min(max(ix, 0), 63);
        const float qc0 = (2.f * (float)iy + 1.f) * (1.f / 64.f) - 1.f;
        const float qc1 = (2.f * (float)ix + 1.f) * (1.f / 64.f) - 1.f;
        const float r0 = (c0 - qc0) * 64.f;
        const float r1 = (c1 - qc1) * 64.f;
        s_idx[t][i] = iy * 64 + ix;
        s_rel[t][0][i] = r0; s_rel[t][1][i] = r1;
        s_area[t][i] = fabsf(r0 * r1) + 1e-9f;
    }
    __syncthreads();

    if (tid < QT) {
        const float a0 = s_area[0][tid], a1 = s_area[1][tid];
        const float a2 = s_area[2][tid], a3 = s_area[3][tid];
        const float tot = a0 + a1 + a2 + a3;
        s_wt[0][tid] = a3 / tot; s_wt[1][tid] = a2 / tot;
        s_wt[2][tid] = a1 / tot; s_wt[3][tid] = a0 / tot;
    }

    // h0 build: thread = (row, 128-col half); P' fp16 -> fp32 math -> fp16
    {
        const int row = tid >> 1, hseg = tid & 1;
        const int t = row >> 5, i = row & 31;
        const int idx = s_idx[t][i];
        const float r0 = s_rel[t][0][i], r1 = s_rel[t][1][i];
        const uint4* pp = (const uint4*)(g_proj_h + (((size_t)n << 12) + idx) * 256
                                         + hseg * 128);
        __half2* xw = (__half2*)Xs + row * 132 + hseg * 64;
#pragma unroll
        for (int j = 0; j < 16; j++) {
            const uint4 q = pp[j];
            uint32_t w[4] = {q.x, q.y, q.z, q.w};
            const int cb = hseg * 128 + j * 8;
#pragma unroll
            for (int u = 0; u < 4; u++) {
                const float2 p = __half22float2(*(const __half2*)&w[u]);
                const int c = cb + 2 * u;
                const float v0 = fmaf(r0, s_w0r[0][c],     fmaf(r1, s_w0r[1][c],     p.x));
                const float v1 = fmaf(r0, s_w0r[0][c + 1], fmaf(r1, s_w0r[1][c + 1], p.y));
                xw[j * 4 + u] = __floats2half2_rn(fmaxf(v0, 0.f), fmaxf(v1, 0.f));
            }
        }
    }
    __syncthreads();

    const int lrow = lane & 15;
    const int kadd = (lane >> 4) << 3;
    const uint32_t a_lane = xs_u + (uint32_t)(lrow * XS_H + kadd) * 2u;
    const uint32_t b_lane = (uint32_t)(lane * 8 + (lane >> 2) * 4) * 4u;   // bytes

    float acc[8][4][4];
#pragma unroll
    for (int mt = 0; mt < 8; mt++)
#pragma unroll
        for (int nt = 0; nt < 4; nt++)
#pragma unroll
            for (int r = 0; r < 4; r++) acc[mt][nt][r] = 0.f;

    int buf = 0;
#pragma unroll 1
    for (int st = 0; st < NSTAGES; st++) {
        const int tile = st & 3;

        if (st + 1 < NSTAGES) { prefetch(buf ^ 1, st + 1); cp_wait<1>(); }
        else                  { cp_wait<0>(); }
        // no __syncthreads: B strips are warp-private, Xs is read-only here

        const uint32_t bbase = bs_u + (uint32_t)((wid * 2 + buf) * BWW) * 4u + b_lane;
        const uint32_t a_st  = a_lane + (uint32_t)(tile * 64) * 2u;

#pragma unroll
        for (int s = 0; s < 4; s++) {            // four k16 steps per 64-k tile
            uint32_t b0f[4], b1f[4];
            {
                const uint32_t baddr = bbase + (uint32_t)(s * 288) * 4u;
                lds128(b0f[0], b1f[0], b0f[1], b1f[1], baddr);
                lds128(b0f[2], b1f[2], b0f[3], b1f[3], baddr + 16u);
            }
            const uint32_t a_s = a_st + (uint32_t)(s * 32);
#pragma unroll
            for (int mt = 0; mt < 8; mt++) {
                uint32_t a0, a1, a2, a3;
                ldsm4(a0, a1, a2, a3, a_s + (uint32_t)(mt * 16 * XS_H * 2));
#pragma unroll
                for (int nt = 0; nt < 4; nt++)
                    mma_f16(acc[mt][nt], a0, a1, a2, a3, b0f[nt], b1f[nt]);
            }
        }
        buf ^= 1;

        if (tile == 3 && st < NSTAGES - 1) {     // layers 1,2 boundary
            const int le = st >> 2;
            __syncthreads();                     // all reads of Xs done
#pragma unroll
            for (int mt = 0; mt < 8; mt++) {
#pragma unroll
                for (int nt = 0; nt < 4; nt++) {
                    const int c = wid * 32 + nt * 8 + 2 * tig;
                    const float bv0 = s_bias[le][c], bv1 = s_bias[le][c + 1];
                    const float v00 = fmaxf(acc[mt][nt][0] + bv0, 0.f);
                    const float v01 = fmaxf(acc[mt][nt][1] + bv1, 0.f);
                    const float v10 = fmaxf(acc[mt][nt][2] + bv0, 0.f);
                    const float v11 = fmaxf(acc[mt][nt][3] + bv1, 0.f);
                    const int r0 = mt * 16 + g_;
                    __half2* xw = (__half2*)Xs;
                    xw[r0 * 132 + wid * 16 + nt * 4 + tig]       = __floats2half2_rn(v00, v01);
                    xw[(r0 + 8) * 132 + wid * 16 + nt * 4 + tig] = __floats2half2_rn(v10, v11);
                    acc[mt][nt][0] = 0.f; acc[mt][nt][1] = 0.f;
                    acc[mt][nt][2] = 0.f; acc[mt][nt][3] = 0.f;
                }
            }
            __syncthreads();                     // writes visible before next layer
        }
    }

    // fused last epilogue + final 256->3 layer: per-thread partial dots.
    // Thread owns cols {c, c+1} x rows {mt*16+g_, +8}; no Xs write needed.
    {
        float p[8][2][3];
#pragma unroll
        for (int mt = 0; mt < 8; mt++)
#pragma unroll
            for (int rh = 0; rh < 2; rh++) {
                p[mt][rh][0] = 0.f; p[mt][rh][1] = 0.f; p[mt][rh][2] = 0.f;
            }
#pragma unroll
        for (int nt = 0; nt < 4; nt++) {
            const int c = wid * 32 + nt * 8 + 2 * tig;
            const float bv0 = s_bias[2][c], bv1 = s_bias[2][c + 1];
            const float* wr0 = &s_w4[c * 3];
            const float* wr1 = &s_w4[(c + 1) * 3];
#pragma unroll
            for (int mt = 0; mt < 8; mt++) {
                const float v00 = fmaxf(acc[mt][nt][0] + bv0, 0.f);
                const float v01 = fmaxf(acc[mt][nt][1] + bv1, 0.f);
                const float v10 = fmaxf(acc[mt][nt][2] + bv0, 0.f);
                const float v11 = fmaxf(acc[mt][nt][3] + bv1, 0.f);
#pragma unroll
                for (int o = 0; o < 3; o++) {
                    p[mt][0][o] = fmaf(v00, wr0[o], fmaf(v01, wr1[o], p[mt][0][o]));
                    p[mt][1][o] = fmaf(v10, wr0[o], fmaf(v11, wr1[o], p[mt][1][o]));
                }
            }
        }
        // warp-internal reduce over tig (4 lanes share each (row, o))
#pragma unroll
        for (int mt = 0; mt < 8; mt++)
#pragma unroll
            for (int rh = 0; rh < 2; rh++)
#pragma unroll
                for (int o = 0; o < 3; o++) {
                    float v = p[mt][rh][o];
                    v += __shfl_xor_sync(0xFFFFFFFFu, v, 1);
                    v += __shfl_xor_sync(0xFFFFFFFFu, v, 2);
                    p[mt][rh][o] = v;
                }
        if (tig == 0) {
#pragma unroll
            for (int mt = 0; mt < 8; mt++) {
                const int r0 = mt * 16 + g_;
#pragma unroll
                for (int o = 0; o < 3; o++) {
                    s_red[r0][wid][o]     = p[mt][0][o];
                    s_red[r0 + 8][wid][o] = p[mt][1][o];
                }
            }
        }
    }
    __syncthreads();

    // area-weighted combine + NCHW write (reduce 8 warp partials per row)
    if (tid < 96) {
        const int i = tid / 3;
        const int o = tid - 3 * (tid / 3);
        float v = 0.f;
#pragma unroll
        for (int t = 0; t < 4; t++) {
            const int row = t * 32 + i;
            float pr = s_b4[o];
#pragma unroll
            for (int w = 0; w < 8; w++) pr += s_red[row][w][o];
            v += s_wt[t][i] * pr;
        }
        out[((size_t)n * 3 + o) * 65536 + q0 + i] = v;
    }
}

} // anonymous namespace

extern "C" void kernel_launch(void* const* d_in, const int* in_sizes, int n_in,
                              void* d_out, int out_size)
{
    (void)in_sizes; (void)n_in; (void)out_size;
    const float* feat = (const float*)d_in[0];
    const float* w0 = (const float*)d_in[1];
    const float* b0 = (const float*)d_in[2];
    const float* w1 = (const float*)d_in[3];
    const float* b1 = (const float*)d_in[4];
    const float* w2 = (const float*)d_in[5];
    const float* b2 = (const float*)d_in[6];
    const float* w3 = (const float*)d_in[7];
    const float* b3 = (const float*)d_in[8];
    const float* w4 = (const float*)d_in[9];
    const float* b4 = (const float*)d_in[10];

    const size_t prep_shmem = (128 * 72 + 8 * 32 * 72) * sizeof(__half)
                            + 256 * sizeof(float);               // 56320 B
    cudaFuncSetAttribute(prep_kernel,
                         cudaFuncAttributeMaxDynamicSharedMemorySize, (int)prep_shmem);
    prep_kernel<<<128 + 384, 256, prep_shmem>>>(feat, w0, b0, w1, w2, w3);

    const size_t shmem = (size_t)(128 * XS_H) * sizeof(__half)
                       + (size_t)(8 * 2 * BWW) * sizeof(uint32_t); // 141312 B
    cudaFuncSetAttribute(liif_hmma_kernel,
                         cudaFuncAttributeMaxDynamicSharedMemorySize, (int)shmem);
    dim3 grid(65536 / QT, 4);
    liif_hmma_kernel<<<grid, NTHR, shmem>>>(w0, w4, b1, b2, b3, b4, (float*)d_out);
}